// round 1
// baseline (speedup 1.0000x reference)
#include <cuda_runtime.h>

namespace {

constexpr int NFREQ = 6;
constexpr int CIN   = 3 + 3 * 2 * NFREQ + 2 * 16;  // 71
constexpr int HID   = 32;
constexpr int NC    = 16;
constexpr int TPB   = 128;

struct Params {
  const float* p;
  const float* bound;
  const float* pl[12];  // geo: xy0,xz0,yz0,xy1,xz1,yz1 | col: xy0,xz0,yz0,xy1,xz1,yz1
  const float* W0;  const float* b0;
  const float* W1;  const float* b1;
  const float* Wo;  const float* bo;
  const float* cW0; const float* cb0;
  const float* cW1; const float* cb1;
  const float* cWo; const float* cbo;
  float* out;
  int N;
};

// Bilinear grid_sample (border clamp, align_corners=True), accumulate 16 channels.
template <int R>
__device__ __forceinline__ void sample_add(const float* __restrict__ pl,
                                           float gx, float gy, float* acc) {
  const float rm1 = (float)(R - 1);
  float ix = fminf(fmaxf((gx + 1.0f) * 0.5f * rm1, 0.0f), rm1);
  float iy = fminf(fmaxf((gy + 1.0f) * 0.5f * rm1, 0.0f), rm1);
  float fx0 = floorf(ix), fy0 = floorf(iy);
  int x0 = (int)fx0, y0 = (int)fy0;
  int x1 = min(x0 + 1, R - 1);
  int y1 = min(y0 + 1, R - 1);
  float wx = ix - fx0, wy = iy - fy0;
  float w00 = (1.0f - wx) * (1.0f - wy);
  float w01 = wx * (1.0f - wy);
  float w10 = (1.0f - wx) * wy;
  float w11 = wx * wy;
  int o00 = y0 * R + x0, o01 = y0 * R + x1;
  int o10 = y1 * R + x0, o11 = y1 * R + x1;
#pragma unroll
  for (int c = 0; c < NC; c++) {
    const float* b = pl + c * R * R;
    acc[c] += w00 * __ldg(b + o00) + w01 * __ldg(b + o01) +
              w10 * __ldg(b + o10) + w11 * __ldg(b + o11);
  }
}

__global__ __launch_bounds__(TPB) void decoder_kernel(Params P) {
  __shared__ float sW0[HID * CIN];
  __shared__ float sW1[HID * HID];
  __shared__ float scW0[HID * CIN];
  __shared__ float scW1[HID * HID];
  __shared__ float sb0[HID], sb1[HID], sWo[HID];
  __shared__ float scb0[HID], scb1[HID], scWo[3 * HID];
  __shared__ float sbo, scbo[3];

  const int t = threadIdx.x;
  for (int i = t; i < HID * CIN; i += TPB) { sW0[i] = P.W0[i]; scW0[i] = P.cW0[i]; }
  for (int i = t; i < HID * HID; i += TPB) { sW1[i] = P.W1[i]; scW1[i] = P.cW1[i]; }
  if (t < HID) {
    sb0[t] = P.b0[t]; sb1[t] = P.b1[t]; sWo[t] = P.Wo[t];
    scb0[t] = P.cb0[t]; scb1[t] = P.cb1[t];
  }
  for (int i = t; i < 3 * HID; i += TPB) scWo[i] = P.cWo[i];
  if (t == 0) sbo = P.bo[0];
  if (t < 3) scbo[t] = P.cbo[t];
  __syncthreads();

  const int idx = blockIdx.x * TPB + t;
  if (idx >= P.N) return;

  float px = P.p[3 * idx + 0];
  float py = P.p[3 * idx + 1];
  float pz = P.p[3 * idx + 2];
  float lo0 = __ldg(P.bound + 0), hi0 = __ldg(P.bound + 1);
  float lo1 = __ldg(P.bound + 2), hi1 = __ldg(P.bound + 3);
  float lo2 = __ldg(P.bound + 4), hi2 = __ldg(P.bound + 5);
  float nx = (px - lo0) / (hi0 - lo0);
  float ny = (py - lo1) / (hi1 - lo1);
  float nz = (pz - lo2) / (hi2 - lo2);

  float x[CIN];
  x[0] = nx; x[1] = ny; x[2] = nz;
  float n3[3] = {nx, ny, nz};
#pragma unroll
  for (int f = 0; f < NFREQ; f++) {
    const float freq = 3.14159265358979323846f * (float)(1 << f);
#pragma unroll
    for (int a = 0; a < 3; a++) {
      float s, c;
      sincosf(n3[a] * freq, &s, &c);
      x[3 + f * 3 + a] = s;
      x[3 + 18 + f * 3 + a] = c;
    }
  }

  // ---------------- geometry branch ----------------
#pragma unroll
  for (int c = 0; c < 2 * NC; c++) x[39 + c] = 0.0f;
  sample_add<512>(P.pl[0], nx, ny, x + 39);
  sample_add<512>(P.pl[1], nx, nz, x + 39);
  sample_add<512>(P.pl[2], ny, nz, x + 39);
  sample_add<1024>(P.pl[3], nx, ny, x + 39 + NC);
  sample_add<1024>(P.pl[4], nx, nz, x + 39 + NC);
  sample_add<1024>(P.pl[5], ny, nz, x + 39 + NC);

  float h1[HID], h2[HID];
  for (int j = 0; j < HID; j++) {
    float s = sb0[j];
#pragma unroll
    for (int i = 0; i < CIN; i++) s += x[i] * sW0[j * CIN + i];
    h1[j] = fmaxf(s, 0.0f);
  }
  for (int j = 0; j < HID; j++) {
    float s = sb1[j];
#pragma unroll
    for (int i = 0; i < HID; i++) s += h1[i] * sW1[j * HID + i];
    h2[j] = fmaxf(s, 0.0f);
  }
  float sdf = sbo;
#pragma unroll
  for (int i = 0; i < HID; i++) sdf += h2[i] * sWo[i];
  sdf = tanhf(sdf);

  // ---------------- color branch ----------------
#pragma unroll
  for (int c = 0; c < 2 * NC; c++) x[39 + c] = 0.0f;
  sample_add<512>(P.pl[6], nx, ny, x + 39);
  sample_add<512>(P.pl[7], nx, nz, x + 39);
  sample_add<512>(P.pl[8], ny, nz, x + 39);
  sample_add<1024>(P.pl[9],  nx, ny, x + 39 + NC);
  sample_add<1024>(P.pl[10], nx, nz, x + 39 + NC);
  sample_add<1024>(P.pl[11], ny, nz, x + 39 + NC);

  for (int j = 0; j < HID; j++) {
    float s = scb0[j];
#pragma unroll
    for (int i = 0; i < CIN; i++) s += x[i] * scW0[j * CIN + i];
    h1[j] = fmaxf(s, 0.0f);
  }
  for (int j = 0; j < HID; j++) {
    float s = scb1[j];
#pragma unroll
    for (int i = 0; i < HID; i++) s += h1[i] * scW1[j * HID + i];
    h2[j] = fmaxf(s, 0.0f);
  }
  float r = scbo[0], g = scbo[1], b = scbo[2];
#pragma unroll
  for (int i = 0; i < HID; i++) {
    r += h2[i] * scWo[0 * HID + i];
    g += h2[i] * scWo[1 * HID + i];
    b += h2[i] * scWo[2 * HID + i];
  }

  reinterpret_cast<float4*>(P.out)[idx] = make_float4(r, g, b, sdf);
}

}  // namespace

extern "C" void kernel_launch(void* const* d_in, const int* in_sizes, int n_in,
                              void* d_out, int out_size) {
  Params P;
  P.p     = (const float*)d_in[0];
  P.bound = (const float*)d_in[1];
  for (int i = 0; i < 12; i++) P.pl[i] = (const float*)d_in[2 + i];
  P.W0  = (const float*)d_in[14]; P.b0  = (const float*)d_in[15];
  P.W1  = (const float*)d_in[16]; P.b1  = (const float*)d_in[17];
  P.Wo  = (const float*)d_in[18]; P.bo  = (const float*)d_in[19];
  P.cW0 = (const float*)d_in[20]; P.cb0 = (const float*)d_in[21];
  P.cW1 = (const float*)d_in[22]; P.cb1 = (const float*)d_in[23];
  P.cWo = (const float*)d_in[24]; P.cbo = (const float*)d_in[25];
  P.out = (float*)d_out;
  P.N   = in_sizes[0] / 3;

  dim3 grid((P.N + TPB - 1) / TPB);
  decoder_kernel<<<grid, TPB>>>(P);
}

// round 2
// speedup vs baseline: 2.2970x; 2.2970x over previous
#include <cuda_runtime.h>

namespace {

constexpr int NFREQ = 6;
constexpr int CIN   = 3 + 3 * 2 * NFREQ + 2 * 16;  // 71
constexpr int CINP  = 72;                          // padded to multiple of 4
constexpr int HID   = 32;
constexpr int TPB   = 128;

// Channel-interleaved scratch for all 12 planes: (H, W, C=16) layout.
// sizes: level0 plane = 512*512*16 = 4,194,304 floats; level1 = 1024*1024*16 = 16,777,216
__device__ float g_tp[125829120];  // 480 MB

__device__ constexpr long long PO[12] = {
  0LL,                       // geo xy0 (512)
  4194304LL,                 // geo xz0
  8388608LL,                 // geo yz0
  12582912LL,                // geo xy1 (1024)
  29360128LL,                // geo xz1
  46137344LL,                // geo yz1
  62914560LL,                // col xy0
  67108864LL,                // col xz0
  71303168LL,                // col yz0
  75497472LL,                // col xy1
  92274688LL,                // col xz1
  109051904LL                // col yz1
};

// (C,H,W) -> (H,W,C) transpose. One block = 128 consecutive texels.
__global__ __launch_bounds__(128) void transpose_plane(const float* __restrict__ src,
                                                       long long dstoff, int area) {
  __shared__ float s[16 * 128];
  const int base = blockIdx.x * 128;
  const int t = threadIdx.x;
#pragma unroll
  for (int c = 0; c < 16; c++) s[c * 128 + t] = src[(size_t)c * area + base + t];
  __syncthreads();
  float4* out = reinterpret_cast<float4*>(g_tp + dstoff + (long long)base * 16);
#pragma unroll
  for (int i = t; i < 512; i += 128) {
    int texel = i >> 2;
    int c0 = (i & 3) * 4;
    out[i] = make_float4(s[c0 * 128 + texel], s[(c0 + 1) * 128 + texel],
                         s[(c0 + 2) * 128 + texel], s[(c0 + 3) * 128 + texel]);
  }
}

struct Params {
  const float* p;
  const float* bound;
  const float* W0;  const float* b0;
  const float* W1;  const float* b1;
  const float* Wo;  const float* bo;
  const float* cW0; const float* cb0;
  const float* cW1; const float* cb1;
  const float* cWo; const float* cbo;
  float* out;
  int N;
};

// Bilinear sample from interleaved (H,W,16) plane; accumulate into 4 float4s.
template <int R>
__device__ __forceinline__ void sample_add_t(const float* __restrict__ pl,
                                             float gx, float gy, float4 acc[4]) {
  const float rm1 = (float)(R - 1);
  float ix = fminf(fmaxf((gx + 1.0f) * 0.5f * rm1, 0.0f), rm1);
  float iy = fminf(fmaxf((gy + 1.0f) * 0.5f * rm1, 0.0f), rm1);
  float fx0 = floorf(ix), fy0 = floorf(iy);
  int x0 = (int)fx0, y0 = (int)fy0;
  int x1 = min(x0 + 1, R - 1);
  int y1 = min(y0 + 1, R - 1);
  float wx = ix - fx0, wy = iy - fy0;
  float w00 = (1.0f - wx) * (1.0f - wy);
  float w01 = wx * (1.0f - wy);
  float w10 = (1.0f - wx) * wy;
  float w11 = wx * wy;
  const float4* b00 = reinterpret_cast<const float4*>(pl + ((long long)(y0 * R + x0) << 4));
  const float4* b01 = reinterpret_cast<const float4*>(pl + ((long long)(y0 * R + x1) << 4));
  const float4* b10 = reinterpret_cast<const float4*>(pl + ((long long)(y1 * R + x0) << 4));
  const float4* b11 = reinterpret_cast<const float4*>(pl + ((long long)(y1 * R + x1) << 4));
#pragma unroll
  for (int k = 0; k < 4; k++) {
    float4 v00 = __ldg(b00 + k), v01 = __ldg(b01 + k);
    float4 v10 = __ldg(b10 + k), v11 = __ldg(b11 + k);
    acc[k].x += w00 * v00.x + w01 * v01.x + w10 * v10.x + w11 * v11.x;
    acc[k].y += w00 * v00.y + w01 * v01.y + w10 * v10.y + w11 * v11.y;
    acc[k].z += w00 * v00.z + w01 * v01.z + w10 * v10.z + w11 * v11.z;
    acc[k].w += w00 * v00.w + w01 * v01.w + w10 * v10.w + w11 * v11.w;
  }
}

__global__ __launch_bounds__(TPB) void decoder_kernel(Params P) {
  // Weights in shared, rows padded to 72 floats so dot products use LDS.128.
  __shared__ float sW0[HID * CINP];
  __shared__ float sW1[HID * HID];
  __shared__ float scW0[HID * CINP];
  __shared__ float scW1[HID * HID];
  __shared__ float sb0[HID], sb1[HID], sWo[HID];
  __shared__ float scb0[HID], scb1[HID], scWo[3 * HID];
  __shared__ float sbo, scbo[3];

  const int t = threadIdx.x;
  for (int i = t; i < HID * CINP; i += TPB) {
    int j = i / CINP, c = i % CINP;
    float w  = (c < CIN) ? P.W0[j * CIN + c]  : 0.0f;
    float cw = (c < CIN) ? P.cW0[j * CIN + c] : 0.0f;
    sW0[i] = w; scW0[i] = cw;
  }
  for (int i = t; i < HID * HID; i += TPB) { sW1[i] = P.W1[i]; scW1[i] = P.cW1[i]; }
  if (t < HID) {
    sb0[t] = P.b0[t]; sb1[t] = P.b1[t]; sWo[t] = P.Wo[t];
    scb0[t] = P.cb0[t]; scb1[t] = P.cb1[t];
  }
  for (int i = t; i < 3 * HID; i += TPB) scWo[i] = P.cWo[i];
  if (t == 0) sbo = P.bo[0];
  if (t < 3) scbo[t] = P.cbo[t];
  __syncthreads();

  const int idx = blockIdx.x * TPB + t;
  if (idx >= P.N) return;

  float px = P.p[3 * idx + 0];
  float py = P.p[3 * idx + 1];
  float pz = P.p[3 * idx + 2];
  float lo0 = __ldg(P.bound + 0), hi0 = __ldg(P.bound + 1);
  float lo1 = __ldg(P.bound + 2), hi1 = __ldg(P.bound + 3);
  float lo2 = __ldg(P.bound + 4), hi2 = __ldg(P.bound + 5);
  float nx = (px - lo0) / (hi0 - lo0);
  float ny = (py - lo1) / (hi1 - lo1);
  float nz = (pz - lo2) / (hi2 - lo2);

  float x[CINP];
  x[0] = nx; x[1] = ny; x[2] = nz;
  float n3[3] = {nx, ny, nz};
#pragma unroll
  for (int f = 0; f < NFREQ; f++) {
    const float freq = 3.14159265358979323846f * (float)(1 << f);
#pragma unroll
    for (int a = 0; a < 3; a++) {
      float s, c;
      sincosf(n3[a] * freq, &s, &c);
      x[3 + f * 3 + a] = s;
      x[3 + 18 + f * 3 + a] = c;
    }
  }
  x[CIN] = 0.0f;  // pad

  // ---------------- geometry branch ----------------
  {
    float4 acc[8];
#pragma unroll
    for (int k = 0; k < 8; k++) acc[k] = make_float4(0.f, 0.f, 0.f, 0.f);
    sample_add_t<512>(g_tp + PO[0], nx, ny, acc);
    sample_add_t<512>(g_tp + PO[1], nx, nz, acc);
    sample_add_t<512>(g_tp + PO[2], ny, nz, acc);
    sample_add_t<1024>(g_tp + PO[3], nx, ny, acc + 4);
    sample_add_t<1024>(g_tp + PO[4], nx, nz, acc + 4);
    sample_add_t<1024>(g_tp + PO[5], ny, nz, acc + 4);
#pragma unroll
    for (int k = 0; k < 8; k++) {
      x[39 + 4 * k + 0] = acc[k].x;
      x[39 + 4 * k + 1] = acc[k].y;
      x[39 + 4 * k + 2] = acc[k].z;
      x[39 + 4 * k + 3] = acc[k].w;
    }
  }

  float h1[HID], h2[HID];
  for (int j = 0; j < HID; j++) {
    const float4* wr = reinterpret_cast<const float4*>(sW0 + j * CINP);
    float s = sb0[j];
#pragma unroll
    for (int i4 = 0; i4 < CINP / 4; i4++) {
      float4 w = wr[i4];
      s += x[4 * i4] * w.x + x[4 * i4 + 1] * w.y + x[4 * i4 + 2] * w.z + x[4 * i4 + 3] * w.w;
    }
    h1[j] = fmaxf(s, 0.0f);
  }
  for (int j = 0; j < HID; j++) {
    const float4* wr = reinterpret_cast<const float4*>(sW1 + j * HID);
    float s = sb1[j];
#pragma unroll
    for (int i4 = 0; i4 < HID / 4; i4++) {
      float4 w = wr[i4];
      s += h1[4 * i4] * w.x + h1[4 * i4 + 1] * w.y + h1[4 * i4 + 2] * w.z + h1[4 * i4 + 3] * w.w;
    }
    h2[j] = fmaxf(s, 0.0f);
  }
  float sdf = sbo;
#pragma unroll
  for (int i = 0; i < HID; i++) sdf += h2[i] * sWo[i];
  sdf = tanhf(sdf);

  // ---------------- color branch ----------------
  {
    float4 acc[8];
#pragma unroll
    for (int k = 0; k < 8; k++) acc[k] = make_float4(0.f, 0.f, 0.f, 0.f);
    sample_add_t<512>(g_tp + PO[6], nx, ny, acc);
    sample_add_t<512>(g_tp + PO[7], nx, nz, acc);
    sample_add_t<512>(g_tp + PO[8], ny, nz, acc);
    sample_add_t<1024>(g_tp + PO[9],  nx, ny, acc + 4);
    sample_add_t<1024>(g_tp + PO[10], nx, nz, acc + 4);
    sample_add_t<1024>(g_tp + PO[11], ny, nz, acc + 4);
#pragma unroll
    for (int k = 0; k < 8; k++) {
      x[39 + 4 * k + 0] = acc[k].x;
      x[39 + 4 * k + 1] = acc[k].y;
      x[39 + 4 * k + 2] = acc[k].z;
      x[39 + 4 * k + 3] = acc[k].w;
    }
  }

  for (int j = 0; j < HID; j++) {
    const float4* wr = reinterpret_cast<const float4*>(scW0 + j * CINP);
    float s = scb0[j];
#pragma unroll
    for (int i4 = 0; i4 < CINP / 4; i4++) {
      float4 w = wr[i4];
      s += x[4 * i4] * w.x + x[4 * i4 + 1] * w.y + x[4 * i4 + 2] * w.z + x[4 * i4 + 3] * w.w;
    }
    h1[j] = fmaxf(s, 0.0f);
  }
  for (int j = 0; j < HID; j++) {
    const float4* wr = reinterpret_cast<const float4*>(scW1 + j * HID);
    float s = scb1[j];
#pragma unroll
    for (int i4 = 0; i4 < HID / 4; i4++) {
      float4 w = wr[i4];
      s += h1[4 * i4] * w.x + h1[4 * i4 + 1] * w.y + h1[4 * i4 + 2] * w.z + h1[4 * i4 + 3] * w.w;
    }
    h2[j] = fmaxf(s, 0.0f);
  }
  float r = scbo[0], g = scbo[1], b = scbo[2];
#pragma unroll
  for (int i = 0; i < HID; i++) {
    r += h2[i] * scWo[0 * HID + i];
    g += h2[i] * scWo[1 * HID + i];
    b += h2[i] * scWo[2 * HID + i];
  }

  reinterpret_cast<float4*>(P.out)[idx] = make_float4(r, g, b, sdf);
}

}  // namespace

extern "C" void kernel_launch(void* const* d_in, const int* in_sizes, int n_in,
                              void* d_out, int out_size) {
  // 1) transpose all 12 planes into interleaved scratch
  static const int areas[12] = {
    512 * 512, 512 * 512, 512 * 512, 1024 * 1024, 1024 * 1024, 1024 * 1024,
    512 * 512, 512 * 512, 512 * 512, 1024 * 1024, 1024 * 1024, 1024 * 1024
  };
  static const long long offs[12] = {
    0LL, 4194304LL, 8388608LL, 12582912LL, 29360128LL, 46137344LL,
    62914560LL, 67108864LL, 71303168LL, 75497472LL, 92274688LL, 109051904LL
  };
  for (int i = 0; i < 12; i++) {
    transpose_plane<<<areas[i] / 128, 128>>>((const float*)d_in[2 + i], offs[i], areas[i]);
  }

  // 2) decode
  Params P;
  P.p     = (const float*)d_in[0];
  P.bound = (const float*)d_in[1];
  P.W0  = (const float*)d_in[14]; P.b0  = (const float*)d_in[15];
  P.W1  = (const float*)d_in[16]; P.b1  = (const float*)d_in[17];
  P.Wo  = (const float*)d_in[18]; P.bo  = (const float*)d_in[19];
  P.cW0 = (const float*)d_in[20]; P.cb0 = (const float*)d_in[21];
  P.cW1 = (const float*)d_in[22]; P.cb1 = (const float*)d_in[23];
  P.cWo = (const float*)d_in[24]; P.cbo = (const float*)d_in[25];
  P.out = (float*)d_out;
  P.N   = in_sizes[0] / 3;

  dim3 grid((P.N + TPB - 1) / TPB);
  decoder_kernel<<<grid, TPB>>>(P);
}

// round 4
// speedup vs baseline: 3.4124x; 1.4856x over previous
#include <cuda_runtime.h>
#include <cuda_fp16.h>
#include <cstdint>

namespace {

constexpr int NFREQ = 6;
constexpr int CIN   = 3 + 3 * 2 * NFREQ + 2 * 16;  // 71
constexpr int CINP  = 72;
constexpr int HID   = 32;
constexpr int TPB   = 128;

// Merged geo+col channel-interleaved fp16 planes: (H, W, 32) with ch0-15=geo, ch16-31=col.
// 3 * 512^2 * 32 + 3 * 1024^2 * 32 = 125,829,120 halves (252 MB)
__device__ __half g_tp[125829120];

constexpr long long OFF_XY0 = 0LL;
constexpr long long OFF_XZ0 = 8388608LL;
constexpr long long OFF_YZ0 = 16777216LL;
constexpr long long OFF_XY1 = 25165824LL;
constexpr long long OFF_XZ1 = 58720256LL;
constexpr long long OFF_YZ1 = 92274688LL;

// Pack one (geo, col) plane pair from (C,H,W) fp32 into (H,W,32) fp16.
__global__ __launch_bounds__(128) void pack_pair(const float* __restrict__ geo,
                                                 const float* __restrict__ col,
                                                 long long dstoff, int area) {
  __shared__ float sg[16 * 128];
  __shared__ float sc[16 * 128];
  const int base = blockIdx.x * 128;
  const int t = threadIdx.x;
#pragma unroll
  for (int c = 0; c < 16; c++) {
    sg[c * 128 + t] = geo[(size_t)c * area + base + t];
    sc[c * 128 + t] = col[(size_t)c * area + base + t];
  }
  __syncthreads();
  uint4* out = reinterpret_cast<uint4*>(g_tp + dstoff + (long long)base * 32);
#pragma unroll
  for (int i = t; i < 512; i += 128) {
    int texel = i >> 2, q = i & 3;
    const float* src = (q < 2) ? sg : sc;
    int ch0 = (q & 1) * 8;
    unsigned int u[4];
#pragma unroll
    for (int k = 0; k < 4; k++) {
      __half2 h = __floats2half2_rn(src[(ch0 + 2 * k) * 128 + texel],
                                    src[(ch0 + 2 * k + 1) * 128 + texel]);
      u[k] = *reinterpret_cast<unsigned int*>(&h);
    }
    out[i] = make_uint4(u[0], u[1], u[2], u[3]);
  }
}

struct Params {
  const float* p;
  const float* bound;
  const float* W0;  const float* b0;
  const float* W1;  const float* b1;
  const float* Wo;  const float* bo;
  const float* cW0; const float* cb0;
  const float* cW1; const float* cb1;
  const float* cWo; const float* cbo;
  float* out;
  int N;
};

__device__ __forceinline__ void acc8(uint4 v, float w, float* acc) {
  const __half2* h = reinterpret_cast<const __half2*>(&v);
#pragma unroll
  for (int k = 0; k < 4; k++) {
    float2 f = __half22float2(h[k]);
    acc[2 * k]     += w * f.x;
    acc[2 * k + 1] += w * f.y;
  }
}

// Bilinear sample of merged (H,W,32) fp16 plane -> accumulate geo[16] and col[16].
template <int R>
__device__ __forceinline__ void sample_pair(const __half* __restrict__ pl,
                                            float gx, float gy,
                                            float* g, float* c) {
  const float rm1 = (float)(R - 1);
  float ix = fminf(fmaxf((gx + 1.0f) * 0.5f * rm1, 0.0f), rm1);
  float iy = fminf(fmaxf((gy + 1.0f) * 0.5f * rm1, 0.0f), rm1);
  float fx0 = floorf(ix), fy0 = floorf(iy);
  int x0 = (int)fx0, y0 = (int)fy0;
  int x1 = min(x0 + 1, R - 1);
  int y1 = min(y0 + 1, R - 1);
  float wx = ix - fx0, wy = iy - fy0;
  float w[4] = {(1.0f - wx) * (1.0f - wy), wx * (1.0f - wy),
                (1.0f - wx) * wy,          wx * wy};
  const uint4* cp[4] = {
    reinterpret_cast<const uint4*>(pl + ((size_t)(y0 * R + x0) << 5)),
    reinterpret_cast<const uint4*>(pl + ((size_t)(y0 * R + x1) << 5)),
    reinterpret_cast<const uint4*>(pl + ((size_t)(y1 * R + x0) << 5)),
    reinterpret_cast<const uint4*>(pl + ((size_t)(y1 * R + x1) << 5))};
#pragma unroll
  for (int k = 0; k < 4; k++) {
    uint4 v0 = __ldg(cp[k] + 0);
    uint4 v1 = __ldg(cp[k] + 1);
    uint4 v2 = __ldg(cp[k] + 2);
    uint4 v3 = __ldg(cp[k] + 3);
    acc8(v0, w[k], g);
    acc8(v1, w[k], g + 8);
    acc8(v2, w[k], c);
    acc8(v3, w[k], c + 8);
  }
}

__global__ __launch_bounds__(TPB, 3) void decoder_kernel(Params P) {
  __shared__ float sW0[HID * CINP];
  __shared__ float sW1[HID * HID];
  __shared__ float scW0[HID * CINP];
  __shared__ float scW1[HID * HID];
  __shared__ float sb0[HID], sb1[HID], sWo[HID];
  __shared__ float scb0[HID], scb1[HID], scWo[3 * HID];
  __shared__ float sbo, scbo[3];
  __shared__ float scf[TPB * 33];  // color feats parking, stride 33 = conflict-free

  const int t = threadIdx.x;
  for (int i = t; i < HID * CINP; i += TPB) {
    int j = i / CINP, c = i % CINP;
    sW0[i]  = (c < CIN) ? P.W0[j * CIN + c]  : 0.0f;
    scW0[i] = (c < CIN) ? P.cW0[j * CIN + c] : 0.0f;
  }
  for (int i = t; i < HID * HID; i += TPB) { sW1[i] = P.W1[i]; scW1[i] = P.cW1[i]; }
  if (t < HID) {
    sb0[t] = P.b0[t]; sb1[t] = P.b1[t]; sWo[t] = P.Wo[t];
    scb0[t] = P.cb0[t]; scb1[t] = P.cb1[t];
  }
  for (int i = t; i < 3 * HID; i += TPB) scWo[i] = P.cWo[i];
  if (t == 0) sbo = P.bo[0];
  if (t < 3) scbo[t] = P.cbo[t];
  __syncthreads();

  const int idx = blockIdx.x * TPB + t;
  if (idx >= P.N) return;

  float px = P.p[3 * idx + 0];
  float py = P.p[3 * idx + 1];
  float pz = P.p[3 * idx + 2];
  float lo0 = __ldg(P.bound + 0), hi0 = __ldg(P.bound + 1);
  float lo1 = __ldg(P.bound + 2), hi1 = __ldg(P.bound + 3);
  float lo2 = __ldg(P.bound + 4), hi2 = __ldg(P.bound + 5);
  float nx = (px - lo0) / (hi0 - lo0);
  float ny = (py - lo1) / (hi1 - lo1);
  float nz = (pz - lo2) / (hi2 - lo2);

  // ---- gather first (small live set: nx,ny,nz + accumulators) ----
  float gf[32], cf[32];
#pragma unroll
  for (int k = 0; k < 32; k++) { gf[k] = 0.0f; cf[k] = 0.0f; }
  sample_pair<512>(g_tp + OFF_XY0, nx, ny, gf, cf);
  sample_pair<512>(g_tp + OFF_XZ0, nx, nz, gf, cf);
  sample_pair<512>(g_tp + OFF_YZ0, ny, nz, gf, cf);
  sample_pair<1024>(g_tp + OFF_XY1, nx, ny, gf + 16, cf + 16);
  sample_pair<1024>(g_tp + OFF_XZ1, nx, nz, gf + 16, cf + 16);
  sample_pair<1024>(g_tp + OFF_YZ1, ny, nz, gf + 16, cf + 16);

  // park color feats in smem, freeing registers for the MLP phase
#pragma unroll
  for (int k = 0; k < 32; k++) scf[t * 33 + k] = cf[k];

  // ---- embedding ----
  float x[CINP];
  x[0] = nx; x[1] = ny; x[2] = nz;
  float n3[3] = {nx, ny, nz};
#pragma unroll
  for (int f = 0; f < NFREQ; f++) {
    const float freq = 3.14159265358979323846f * (float)(1 << f);
#pragma unroll
    for (int a = 0; a < 3; a++) {
      float s, c;
      sincosf(n3[a] * freq, &s, &c);
      x[3 + f * 3 + a] = s;
      x[3 + 18 + f * 3 + a] = c;
    }
  }
  x[CIN] = 0.0f;
#pragma unroll
  for (int k = 0; k < 32; k++) x[39 + k] = gf[k];

  // ---- geometry MLP ----
  float h1[HID], h2[HID];
  for (int j = 0; j < HID; j++) {
    const float4* wr = reinterpret_cast<const float4*>(sW0 + j * CINP);
    float s = sb0[j];
#pragma unroll
    for (int i4 = 0; i4 < CINP / 4; i4++) {
      float4 w = wr[i4];
      s += x[4 * i4] * w.x + x[4 * i4 + 1] * w.y + x[4 * i4 + 2] * w.z + x[4 * i4 + 3] * w.w;
    }
    h1[j] = fmaxf(s, 0.0f);
  }
  for (int j = 0; j < HID; j++) {
    const float4* wr = reinterpret_cast<const float4*>(sW1 + j * HID);
    float s = sb1[j];
#pragma unroll
    for (int i4 = 0; i4 < HID / 4; i4++) {
      float4 w = wr[i4];
      s += h1[4 * i4] * w.x + h1[4 * i4 + 1] * w.y + h1[4 * i4 + 2] * w.z + h1[4 * i4 + 3] * w.w;
    }
    h2[j] = fmaxf(s, 0.0f);
  }
  float sdf = sbo;
#pragma unroll
  for (int i = 0; i < HID; i++) sdf += h2[i] * sWo[i];
  sdf = tanhf(sdf);

  // ---- color MLP (reuse emb, swap in color feats) ----
#pragma unroll
  for (int k = 0; k < 32; k++) x[39 + k] = scf[t * 33 + k];

  for (int j = 0; j < HID; j++) {
    const float4* wr = reinterpret_cast<const float4*>(scW0 + j * CINP);
    float s = scb0[j];
#pragma unroll
    for (int i4 = 0; i4 < CINP / 4; i4++) {
      float4 w = wr[i4];
      s += x[4 * i4] * w.x + x[4 * i4 + 1] * w.y + x[4 * i4 + 2] * w.z + x[4 * i4 + 3] * w.w;
    }
    h1[j] = fmaxf(s, 0.0f);
  }
  for (int j = 0; j < HID; j++) {
    const float4* wr = reinterpret_cast<const float4*>(scW1 + j * HID);
    float s = scb1[j];
#pragma unroll
    for (int i4 = 0; i4 < HID / 4; i4++) {
      float4 w = wr[i4];
      s += h1[4 * i4] * w.x + h1[4 * i4 + 1] * w.y + h1[4 * i4 + 2] * w.z + h1[4 * i4 + 3] * w.w;
    }
    h2[j] = fmaxf(s, 0.0f);
  }
  float r = scbo[0], g = scbo[1], b = scbo[2];
#pragma unroll
  for (int i = 0; i < HID; i++) {
    r += h2[i] * scWo[0 * HID + i];
    g += h2[i] * scWo[1 * HID + i];
    b += h2[i] * scWo[2 * HID + i];
  }

  reinterpret_cast<float4*>(P.out)[idx] = make_float4(r, g, b, sdf);
}

}  // namespace

extern "C" void kernel_launch(void* const* d_in, const int* in_sizes, int n_in,
                              void* d_out, int out_size) {
  static const int areas[6] = {512 * 512, 512 * 512, 512 * 512,
                               1024 * 1024, 1024 * 1024, 1024 * 1024};
  static const long long offs[6] = {OFF_XY0, OFF_XZ0, OFF_YZ0,
                                    OFF_XY1, OFF_XZ1, OFF_YZ1};
  for (int i = 0; i < 6; i++) {
    pack_pair<<<areas[i] / 128, 128>>>((const float*)d_in[2 + i],
                                       (const float*)d_in[8 + i],
                                       offs[i], areas[i]);
  }

  Params P;
  P.p     = (const float*)d_in[0];
  P.bound = (const float*)d_in[1];
  P.W0  = (const float*)d_in[14]; P.b0  = (const float*)d_in[15];
  P.W1  = (const float*)d_in[16]; P.b1  = (const float*)d_in[17];
  P.Wo  = (const float*)d_in[18]; P.bo  = (const float*)d_in[19];
  P.cW0 = (const float*)d_in[20]; P.cb0 = (const float*)d_in[21];
  P.cW1 = (const float*)d_in[22]; P.cb1 = (const float*)d_in[23];
  P.cWo = (const float*)d_in[24]; P.cbo = (const float*)d_in[25];
  P.out = (float*)d_out;
  P.N   = in_sizes[0] / 3;

  dim3 grid((P.N + TPB - 1) / TPB);
  decoder_kernel<<<grid, TPB>>>(P);
}